// round 16
// baseline (speedup 1.0000x reference)
#include <cuda_runtime.h>
#include <math.h>
#include <stdint.h>

#define BB 4
#define SS 2048
#define DD 768
#define HH 12
#define DKK 64
#define MTOT (BB*SS)   // 8192
#define NQKV (3*DD)    // 2304

// Scratch (tf32-rounded fp32 bit patterns). Q plane pre-scaled by CEXP.
__device__ float g_qkv[(size_t)3 * BB * HH * SS * DKK];
__device__ float g_obuf[(size_t)BB * SS * DD];
__device__ float g_xr[(size_t)MTOT * DD];
__device__ float g_wqkvr[(size_t)NQKV * DD];
__device__ float g_wor[(size_t)DD * DD];

// ---------------------------------------------------------------------------
// helpers
// ---------------------------------------------------------------------------
__device__ __forceinline__ uint32_t f2tf(float x) {
    uint32_t r;
    asm("cvt.rna.tf32.f32 %0, %1;" : "=r"(r) : "f"(x));
    return r;
}

__device__ __forceinline__ void mma_tf32(float* c, const uint32_t* a, const uint32_t* b) {
    asm volatile(
        "mma.sync.aligned.m16n8k8.row.col.f32.tf32.tf32.f32 "
        "{%0,%1,%2,%3}, {%4,%5,%6,%7}, {%8,%9}, {%0,%1,%2,%3};\n"
        : "+f"(c[0]), "+f"(c[1]), "+f"(c[2]), "+f"(c[3])
        : "r"(a[0]), "r"(a[1]), "r"(a[2]), "r"(a[3]), "r"(b[0]), "r"(b[1]));
}

__device__ __forceinline__ void cp_async16(void* smem, const void* gmem) {
    uint32_t s = (uint32_t)__cvta_generic_to_shared(smem);
    asm volatile("cp.async.cg.shared.global [%0], [%1], 16;\n" :: "r"(s), "l"(gmem));
}
__device__ __forceinline__ void cp_commit() { asm volatile("cp.async.commit_group;\n"); }
template <int N>
__device__ __forceinline__ void cp_wait() { asm volatile("cp.async.wait_group %0;\n" :: "n"(N)); }

// fast 2^x on the FMA/ALU pipes (no MUFU). fexp2(0) == 1.0f exactly.
__device__ __forceinline__ float fexp2(float x) {
    x = fmaxf(x, -120.0f);
    float z = x + 12582912.0f;
    float f = x - (z - 12582912.0f);
    int   i = __float_as_int(z) - 0x4B400000;
    float p = 0.0096818f;
    p = fmaf(p, f, 0.0555041f);
    p = fmaf(p, f, 0.2402265f);
    p = fmaf(p, f, 0.6931472f);
    p = fmaf(p, f, 1.0f);
    return __int_as_float(__float_as_int(p) + (i << 23));
}

#define CEXP 0.1803368801111204f   /* log2(e)/sqrt(64) — folded into Q plane */
#define NEGINF __int_as_float(0xff800000)

// ---------------------------------------------------------------------------
// tf32 pre-rounding pass
// ---------------------------------------------------------------------------
__global__ void preround(float* __restrict__ dst, const float* __restrict__ src, int n4) {
    int i = blockIdx.x * blockDim.x + threadIdx.x;
    if (i < n4) {
        float4 v = ((const float4*)src)[i];
        uint4 u;
        u.x = f2tf(v.x); u.y = f2tf(v.y); u.z = f2tf(v.z); u.w = f2tf(v.w);
        ((uint4*)dst)[i] = u;
    }
}

// ---------------------------------------------------------------------------
// tf32 tensor-core GEMM on PRE-ROUNDED inputs: C = A(M,K) @ W(N,K)^T.
// BM=256, BN=128, BK=64 (12 k-iters); 16 WARPS (4m x 4n), warp tile 64x32
// -> 4 warps/SMSP for latency hiding, ~110 regs/thread.
// 2-stage cp.async double buffer. Row stride 68 words (conflict-free).
// ---------------------------------------------------------------------------
#define GSTAGES 2
#define GSTRIDE 68
#define GASLOT (256 * GSTRIDE)
#define GBSLOT (128 * GSTRIDE)
#define GEMM_SMEM (GSTAGES * (GASLOT + GBSLOT) * 4)

template <int REMAP>
__global__ __launch_bounds__(512, 1) void gemm_tf32(const float* __restrict__ A,
                                                    const float* __restrict__ W,
                                                    float* __restrict__ C,
                                                    int M, int N, int K) {
    extern __shared__ uint32_t gsm[];
    uint32_t* As = gsm;
    uint32_t* Bs = gsm + GSTAGES * GASLOT;

    const int tid  = threadIdx.x;
    const int lane = tid & 31;
    const int wid  = tid >> 5;
    const int wm   = wid >> 2;      // 0..3
    const int wn   = wid & 3;       // 0..3
    const int m0   = blockIdx.y * 256;
    const int n0   = blockIdx.x * 128;

    const int NT = K / 64;

    float c[4][4][4];
#pragma unroll
    for (int mt = 0; mt < 4; mt++)
#pragma unroll
        for (int nt = 0; nt < 4; nt++)
#pragma unroll
            for (int j = 0; j < 4; j++) c[mt][nt][j] = 0.0f;

    // tile loader (512 thr): A 256x64f (8 chunks/thr), B 128x64f (4 chunks/thr)
    auto load_tile = [&](int kt, uint32_t* as, uint32_t* bs) {
        const float* Ab = A + (size_t)m0 * K + kt * 64;
        const float* Bb = W + (size_t)n0 * K + kt * 64;
#pragma unroll
        for (int i = 0; i < 8; i++) {
            const int ch = tid + i * 512;
            const int row = ch >> 4, c4 = (ch & 15) * 4;
            cp_async16(&as[row * GSTRIDE + c4], Ab + (size_t)row * K + c4);
        }
#pragma unroll
        for (int i = 0; i < 4; i++) {
            const int ch = tid + i * 512;
            const int row = ch >> 4, c4 = (ch & 15) * 4;
            cp_async16(&bs[row * GSTRIDE + c4], Bb + (size_t)row * K + c4);
        }
    };

    load_tile(0, As, Bs);
    cp_commit();

    for (int kt = 0; kt < NT; kt++) {
        cp_wait<0>();
        __syncthreads();

        if (kt + 1 < NT) {
            const int slot = (kt + 1) & 1;
            load_tile(kt + 1, As + slot * GASLOT, Bs + slot * GBSLOT);
        }
        cp_commit();

        const uint32_t* as = As + (kt & 1) * GASLOT;
        const uint32_t* bs = Bs + (kt & 1) * GBSLOT;

#pragma unroll
        for (int k0 = 0; k0 < 64; k0 += 8) {
            uint32_t af[4][4];
#pragma unroll
            for (int mt = 0; mt < 4; mt++) {
                const int row = wm * 64 + mt * 16 + (lane >> 2);
                af[mt][0] = as[row * GSTRIDE + k0 + (lane & 3)];
                af[mt][1] = as[(row + 8) * GSTRIDE + k0 + (lane & 3)];
                af[mt][2] = as[row * GSTRIDE + k0 + 4 + (lane & 3)];
                af[mt][3] = as[(row + 8) * GSTRIDE + k0 + 4 + (lane & 3)];
            }
            uint32_t bf[4][2];
#pragma unroll
            for (int nt = 0; nt < 4; nt++) {
                const int col = wn * 32 + nt * 8 + (lane >> 2);
                bf[nt][0] = bs[col * GSTRIDE + k0 + (lane & 3)];
                bf[nt][1] = bs[col * GSTRIDE + k0 + 4 + (lane & 3)];
            }
#pragma unroll
            for (int mt = 0; mt < 4; mt++)
#pragma unroll
                for (int nt = 0; nt < 4; nt++)
                    mma_tf32(c[mt][nt], af[mt], bf[nt]);
        }
    }

    // epilogue
#pragma unroll
    for (int mt = 0; mt < 4; mt++) {
#pragma unroll
        for (int half = 0; half < 2; half++) {
            const int m = m0 + wm * 64 + mt * 16 + (lane >> 2) + half * 8;
#pragma unroll
            for (int nt = 0; nt < 4; nt++) {
                const int n = n0 + wn * 32 + nt * 8 + 2 * (lane & 3);
                float v0 = c[mt][nt][2 * half + 0];
                float v1 = c[mt][nt][2 * half + 1];
                if (REMAP) {
                    const int t = (n >= 2 * DD) ? 2 : ((n >= DD) ? 1 : 0);
                    if (t == 0) { v0 *= CEXP; v1 *= CEXP; }   // fold softmax scale into Q
                    const int r = n - t * DD;
                    const int hh = r >> 6;
                    const int e = r & 63;
                    const int bb = m >> 11;
                    const int ss = m & 2047;
                    size_t idx = ((((size_t)t * BB + bb) * HH + hh) * SS + ss) * DKK + e;
                    uint2 u;
                    u.x = f2tf(v0);
                    u.y = f2tf(v1);
                    *(uint2*)&g_qkv[idx] = u;
                } else {
                    float2 v = make_float2(v0, v1);
                    *(float2*)&C[(size_t)m * N + n] = v;
                }
            }
        }
    }
}

// ---------------------------------------------------------------------------
// Tensor-core causal flash attention (R14/R15-proven, unchanged).
// Br=128, Bc=64, dk=64; 128 threads = 4 warps; warp tile 32x64.
// Q pre-scaled (exp2 domain). Rescale-skip. smem 104448 B -> 2 CTAs/SM.
// ---------------------------------------------------------------------------
__global__ __launch_bounds__(128, 2) void attn_tc() {
    extern __shared__ uint32_t smx[];
    uint32_t* Qs = smx;                        // [128][68]
    uint32_t* Ks = smx + 128 * 68;             // [64][68]
    uint32_t* Vs = smx + 192 * 68;             // [64][68]
    uint32_t* Ps = smx + 256 * 68;             // [128][68]

    const int qt = (SS / 128 - 1) - blockIdx.x;   // largest work first
    const int h  = blockIdx.y;
    const int b  = blockIdx.z;
    const int tid  = threadIdx.x;
    const int lane = tid & 31;
    const int wm   = tid >> 5;   // 0..3

    const size_t plane = (size_t)BB * HH * SS * DKK;
    const size_t bh = (size_t)b * HH + h;
    const float* Qg = g_qkv + 0 * plane + bh * SS * DKK;
    const float* Kg = g_qkv + 1 * plane + bh * SS * DKK;
    const float* Vg = g_qkv + 2 * plane + bh * SS * DKK;

    const int lrow = tid >> 4;           // 0..7
    const int lc4  = (tid & 15) << 2;

#pragma unroll
    for (int i = 0; i < 16; i++) {
        const int row = lrow + i * 8;
        cp_async16(&Qs[row * 68 + lc4], Qg + ((size_t)(qt * 128 + row) << 6) + lc4);
    }
    cp_commit();
#pragma unroll
    for (int i = 0; i < 8; i++) {
        const int row = lrow + i * 8;
        cp_async16(&Ks[row * 68 + lc4], Kg + ((size_t)row << 6) + lc4);
    }
    cp_commit();
#pragma unroll
    for (int i = 0; i < 8; i++) {
        const int row = lrow + i * 8;
        cp_async16(&Vs[row * 68 + lc4], Vg + ((size_t)row << 6) + lc4);
    }
    cp_commit();

    float m_run[4], l_run[4], o[2][8][4];
#pragma unroll
    for (int r = 0; r < 4; r++) { m_run[r] = NEGINF; l_run[r] = 0.0f; }
#pragma unroll
    for (int mt = 0; mt < 2; mt++)
#pragma unroll
        for (int nt = 0; nt < 8; nt++)
#pragma unroll
            for (int j = 0; j < 4; j++) o[mt][nt][j] = 0.0f;

    const int ktmax = 2 * qt + 1;
    for (int kt = 0; kt <= ktmax; kt++) {
        cp_wait<1>();
        __syncthreads();

        float s[2][8][4];
#pragma unroll
        for (int mt = 0; mt < 2; mt++)
#pragma unroll
            for (int nt = 0; nt < 8; nt++)
#pragma unroll
                for (int j = 0; j < 4; j++) s[mt][nt][j] = 0.0f;

#pragma unroll
        for (int k0 = 0; k0 < 64; k0 += 8) {
            uint32_t af[2][4];
#pragma unroll
            for (int mt = 0; mt < 2; mt++) {
                const int row = wm * 32 + mt * 16 + (lane >> 2);
                af[mt][0] = Qs[row * 68 + k0 + (lane & 3)];
                af[mt][1] = Qs[(row + 8) * 68 + k0 + (lane & 3)];
                af[mt][2] = Qs[row * 68 + k0 + 4 + (lane & 3)];
                af[mt][3] = Qs[(row + 8) * 68 + k0 + 4 + (lane & 3)];
            }
            uint32_t bf[8][2];
#pragma unroll
            for (int nt = 0; nt < 8; nt++) {
                const int col = nt * 8 + (lane >> 2);
                bf[nt][0] = Ks[col * 68 + k0 + (lane & 3)];
                bf[nt][1] = Ks[col * 68 + k0 + 4 + (lane & 3)];
            }
#pragma unroll
            for (int mt = 0; mt < 2; mt++)
#pragma unroll
                for (int nt = 0; nt < 8; nt++)
                    mma_tf32(s[mt][nt], af[mt], bf[nt]);
        }

        if (kt >= 2 * qt) {
#pragma unroll
            for (int mt = 0; mt < 2; mt++)
#pragma unroll
                for (int cc = 0; cc < 4; cc++) {
                    const int row_g = qt * 128 + wm * 32 + mt * 16 + (lane >> 2) + 8 * (cc >> 1);
#pragma unroll
                    for (int nt = 0; nt < 8; nt++) {
                        const int col_g = kt * 64 + nt * 8 + 2 * (lane & 3) + (cc & 1);
                        if (col_g > row_g) s[mt][nt][cc] = NEGINF;
                    }
                }
        }

        // online softmax in exp2 domain (Q pre-scaled); rescale-skip
#pragma unroll
        for (int mt = 0; mt < 2; mt++)
#pragma unroll
            for (int half = 0; half < 2; half++) {
                const int rid = mt * 2 + half;
                float mv = NEGINF;
#pragma unroll
                for (int nt = 0; nt < 8; nt++)
                    mv = fmaxf(mv, fmaxf(s[mt][nt][2 * half], s[mt][nt][2 * half + 1]));
                mv = fmaxf(mv, __shfl_xor_sync(0xffffffffu, mv, 1));
                mv = fmaxf(mv, __shfl_xor_sync(0xffffffffu, mv, 2));
                const float mn = fmaxf(m_run[rid], mv);
                const bool same = (mn == m_run[rid]);
                float rs = 0.0f;
#pragma unroll
                for (int nt = 0; nt < 8; nt++)
#pragma unroll
                    for (int j = 0; j < 2; j++) {
                        float p = fexp2(s[mt][nt][2 * half + j] - mn);
                        s[mt][nt][2 * half + j] = p;
                        rs += p;
                    }
                rs += __shfl_xor_sync(0xffffffffu, rs, 1);
                rs += __shfl_xor_sync(0xffffffffu, rs, 2);
                if (same) {
                    l_run[rid] += rs;
                } else {
                    const float sc = fexp2(m_run[rid] - mn);
                    m_run[rid] = mn;
                    l_run[rid] = l_run[rid] * sc + rs;
#pragma unroll
                    for (int nt = 0; nt < 8; nt++)
#pragma unroll
                        for (int j = 0; j < 2; j++) o[mt][nt][2 * half + j] *= sc;
                }
            }

#pragma unroll
        for (int mt = 0; mt < 2; mt++)
#pragma unroll
            for (int half = 0; half < 2; half++) {
                const int row = wm * 32 + mt * 16 + (lane >> 2) + 8 * half;
#pragma unroll
                for (int nt = 0; nt < 8; nt++) {
                    const int col = nt * 8 + 2 * (lane & 3);
                    uint2 u;
                    u.x = f2tf(s[mt][nt][2 * half]);
                    u.y = f2tf(s[mt][nt][2 * half + 1]);
                    *(uint2*)&Ps[row * 68 + col] = u;
                }
            }
        __syncthreads();

        if (kt < ktmax) {
#pragma unroll
            for (int i = 0; i < 8; i++) {
                const int row = lrow + i * 8;
                cp_async16(&Ks[row * 68 + lc4],
                           Kg + ((size_t)((kt + 1) * 64 + row) << 6) + lc4);
            }
        }
        cp_commit();

        cp_wait<1>();
        __syncthreads();

#pragma unroll
        for (int k0 = 0; k0 < 64; k0 += 8) {
            uint32_t af[2][4];
#pragma unroll
            for (int mt = 0; mt < 2; mt++) {
                const int row = wm * 32 + mt * 16 + (lane >> 2);
                af[mt][0] = Ps[row * 68 + k0 + (lane & 3)];
                af[mt][1] = Ps[(row + 8) * 68 + k0 + (lane & 3)];
                af[mt][2] = Ps[row * 68 + k0 + 4 + (lane & 3)];
                af[mt][3] = Ps[(row + 8) * 68 + k0 + 4 + (lane & 3)];
            }
            uint32_t bf[8][2];
#pragma unroll
            for (int nt = 0; nt < 8; nt++) {
                const int col = nt * 8 + (lane >> 2);
                bf[nt][0] = Vs[(k0 + (lane & 3)) * 68 + col];
                bf[nt][1] = Vs[(k0 + 4 + (lane & 3)) * 68 + col];
            }
#pragma unroll
            for (int mt = 0; mt < 2; mt++)
#pragma unroll
                for (int nt = 0; nt < 8; nt++)
                    mma_tf32(o[mt][nt], af[mt], bf[nt]);
        }
        __syncthreads();

        if (kt < ktmax) {
#pragma unroll
            for (int i = 0; i < 8; i++) {
                const int row = lrow + i * 8;
                cp_async16(&Vs[row * 68 + lc4],
                           Vg + ((size_t)((kt + 1) * 64 + row) << 6) + lc4);
            }
        }
        cp_commit();
    }

    // epilogue: normalize, tf32-round, write g_obuf[b][s][d]
#pragma unroll
    for (int mt = 0; mt < 2; mt++)
#pragma unroll
        for (int half = 0; half < 2; half++) {
            const int rid = mt * 2 + half;
            const float inv = 1.0f / l_run[rid];
            const int row = qt * 128 + wm * 32 + mt * 16 + (lane >> 2) + 8 * half;
#pragma unroll
            for (int nt = 0; nt < 8; nt++) {
                const int d = h * 64 + nt * 8 + 2 * (lane & 3);
                uint2 u;
                u.x = f2tf(o[mt][nt][2 * half] * inv);
                u.y = f2tf(o[mt][nt][2 * half + 1] * inv);
                *(uint2*)&g_obuf[((size_t)b * SS + row) * DD + d] = u;
            }
        }
}

#define ATTN_SMEM (384 * 68 * 4)

// ---------------------------------------------------------------------------
extern "C" void kernel_launch(void* const* d_in, const int* in_sizes, int n_in,
                              void* d_out, int out_size) {
    const float* x   = (const float*)d_in[0];  // (4, 2048, 768)
    const float* wqk = (const float*)d_in[1];  // (3, 768, 768)
    const float* wo  = (const float*)d_in[2];  // (768, 768)
    float* out = (float*)d_out;                // (4, 2048, 768)
    (void)in_sizes; (void)n_in; (void)out_size;

    float *xr, *wqkvr, *wor, *obuf;
    cudaGetSymbolAddress((void**)&xr, g_xr);
    cudaGetSymbolAddress((void**)&wqkvr, g_wqkvr);
    cudaGetSymbolAddress((void**)&wor, g_wor);
    cudaGetSymbolAddress((void**)&obuf, g_obuf);

    cudaFuncSetAttribute(gemm_tf32<1>, cudaFuncAttributeMaxDynamicSharedMemorySize, GEMM_SMEM);
    cudaFuncSetAttribute(gemm_tf32<0>, cudaFuncAttributeMaxDynamicSharedMemorySize, GEMM_SMEM);
    cudaFuncSetAttribute(attn_tc, cudaFuncAttributeMaxDynamicSharedMemorySize, ATTN_SMEM);

    // 0) pre-round inputs/weights to tf32
    {
        int n4x = MTOT * DD / 4, n4q = NQKV * DD / 4, n4o = DD * DD / 4;
        preround<<<(n4x + 255) / 256, 256>>>(xr, x, n4x);
        preround<<<(n4q + 255) / 256, 256>>>(wqkvr, wqk, n4q);
        preround<<<(n4o + 255) / 256, 256>>>(wor, wo, n4o);
    }

    // 1) QKV projection -> g_qkv (remapped, rounded, Q scaled by CEXP)
    gemm_tf32<1><<<dim3(NQKV / 128, MTOT / 256), 512, GEMM_SMEM>>>(xr, wqkvr, nullptr, MTOT, NQKV, DD);

    // 2) Causal attention -> g_obuf (rounded)
    attn_tc<<<dim3(SS / 128, HH, BB), 128, ATTN_SMEM>>>();

    // 3) O projection -> out
    gemm_tf32<0><<<dim3(DD / 128, MTOT / 256), 512, GEMM_SMEM>>>(obuf, wor, out, MTOT, DD, DD);
}

// round 17
// speedup vs baseline: 1.0380x; 1.0380x over previous
#include <cuda_runtime.h>
#include <math.h>
#include <stdint.h>

#define BB 4
#define SS 2048
#define DD 768
#define HH 12
#define DKK 64
#define MTOT (BB*SS)   // 8192
#define NQKV (3*DD)    // 2304

// Scratch (tf32-rounded fp32 bit patterns). Q plane pre-scaled by CEXP.
__device__ float g_qkv[(size_t)3 * BB * HH * SS * DKK];
__device__ float g_obuf[(size_t)BB * SS * DD];
__device__ float g_xr[(size_t)MTOT * DD];
__device__ float g_wqkvr[(size_t)NQKV * DD];
__device__ float g_wor[(size_t)DD * DD];

// ---------------------------------------------------------------------------
// helpers
// ---------------------------------------------------------------------------
__device__ __forceinline__ uint32_t f2tf(float x) {
    uint32_t r;
    asm("cvt.rna.tf32.f32 %0, %1;" : "=r"(r) : "f"(x));
    return r;
}

__device__ __forceinline__ void mma_tf32(float* c, const uint32_t* a, const uint32_t* b) {
    asm volatile(
        "mma.sync.aligned.m16n8k8.row.col.f32.tf32.tf32.f32 "
        "{%0,%1,%2,%3}, {%4,%5,%6,%7}, {%8,%9}, {%0,%1,%2,%3};\n"
        : "+f"(c[0]), "+f"(c[1]), "+f"(c[2]), "+f"(c[3])
        : "r"(a[0]), "r"(a[1]), "r"(a[2]), "r"(a[3]), "r"(b[0]), "r"(b[1]));
}

__device__ __forceinline__ void cp_async16(void* smem, const void* gmem) {
    uint32_t s = (uint32_t)__cvta_generic_to_shared(smem);
    asm volatile("cp.async.cg.shared.global [%0], [%1], 16;\n" :: "r"(s), "l"(gmem));
}
__device__ __forceinline__ void cp_commit() { asm volatile("cp.async.commit_group;\n"); }
template <int N>
__device__ __forceinline__ void cp_wait() { asm volatile("cp.async.wait_group %0;\n" :: "n"(N)); }

// fast 2^x on the FMA/ALU pipes (no MUFU). fexp2(0) == 1.0f exactly.
__device__ __forceinline__ float fexp2(float x) {
    x = fmaxf(x, -120.0f);
    float z = x + 12582912.0f;
    float f = x - (z - 12582912.0f);
    int   i = __float_as_int(z) - 0x4B400000;
    float p = 0.0096818f;
    p = fmaf(p, f, 0.0555041f);
    p = fmaf(p, f, 0.2402265f);
    p = fmaf(p, f, 0.6931472f);
    p = fmaf(p, f, 1.0f);
    return __int_as_float(__float_as_int(p) + (i << 23));
}

#define CEXP 0.1803368801111204f   /* log2(e)/sqrt(64) — folded into Q plane */
#define NEGINF __int_as_float(0xff800000)

// ---------------------------------------------------------------------------
// tf32 pre-rounding pass
// ---------------------------------------------------------------------------
__global__ void preround(float* __restrict__ dst, const float* __restrict__ src, int n4) {
    int i = blockIdx.x * blockDim.x + threadIdx.x;
    if (i < n4) {
        float4 v = ((const float4*)src)[i];
        uint4 u;
        u.x = f2tf(v.x); u.y = f2tf(v.y); u.z = f2tf(v.z); u.w = f2tf(v.w);
        ((uint4*)dst)[i] = u;
    }
}

// ---------------------------------------------------------------------------
// tf32 tensor-core GEMM (QKV): C = A(M,K) @ W(N,K)^T.
// BM=256, BN=128, BK=64 (12 k-iters); 8 warps (4x2), warp 64x64.
// 2-stage cp.async double buffer. Row stride 68 words. (R15-proven)
// ---------------------------------------------------------------------------
#define GSTAGES 2
#define GSTRIDE 68
#define GASLOT (256 * GSTRIDE)
#define GBSLOT (128 * GSTRIDE)
#define GEMM_SMEM (GSTAGES * (GASLOT + GBSLOT) * 4)

__global__ __launch_bounds__(256, 1) void gemm_qkv(const float* __restrict__ A,
                                                   const float* __restrict__ W,
                                                   int M, int N, int K) {
    extern __shared__ uint32_t gsm[];
    uint32_t* As = gsm;
    uint32_t* Bs = gsm + GSTAGES * GASLOT;

    const int tid  = threadIdx.x;
    const int lane = tid & 31;
    const int wid  = tid >> 5;
    const int wm   = wid >> 1;
    const int wn   = wid & 1;
    const int m0   = blockIdx.y * 256;
    const int n0   = blockIdx.x * 128;

    const int NT = K / 64;

    float c[4][8][4];
#pragma unroll
    for (int mt = 0; mt < 4; mt++)
#pragma unroll
        for (int nt = 0; nt < 8; nt++)
#pragma unroll
            for (int j = 0; j < 4; j++) c[mt][nt][j] = 0.0f;

    auto load_tile = [&](int kt, uint32_t* as, uint32_t* bs) {
        const float* Ab = A + (size_t)m0 * K + kt * 64;
        const float* Bb = W + (size_t)n0 * K + kt * 64;
#pragma unroll
        for (int i = 0; i < 16; i++) {
            const int ch = tid + i * 256;
            const int row = ch >> 4, c4 = (ch & 15) * 4;
            cp_async16(&as[row * GSTRIDE + c4], Ab + (size_t)row * K + c4);
        }
#pragma unroll
        for (int i = 0; i < 8; i++) {
            const int ch = tid + i * 256;
            const int row = ch >> 4, c4 = (ch & 15) * 4;
            cp_async16(&bs[row * GSTRIDE + c4], Bb + (size_t)row * K + c4);
        }
    };

    load_tile(0, As, Bs);
    cp_commit();

    for (int kt = 0; kt < NT; kt++) {
        cp_wait<0>();
        __syncthreads();

        if (kt + 1 < NT) {
            const int slot = (kt + 1) & 1;
            load_tile(kt + 1, As + slot * GASLOT, Bs + slot * GBSLOT);
        }
        cp_commit();

        const uint32_t* as = As + (kt & 1) * GASLOT;
        const uint32_t* bs = Bs + (kt & 1) * GBSLOT;

#pragma unroll
        for (int k0 = 0; k0 < 64; k0 += 8) {
            uint32_t af[4][4];
#pragma unroll
            for (int mt = 0; mt < 4; mt++) {
                const int row = wm * 64 + mt * 16 + (lane >> 2);
                af[mt][0] = as[row * GSTRIDE + k0 + (lane & 3)];
                af[mt][1] = as[(row + 8) * GSTRIDE + k0 + (lane & 3)];
                af[mt][2] = as[row * GSTRIDE + k0 + 4 + (lane & 3)];
                af[mt][3] = as[(row + 8) * GSTRIDE + k0 + 4 + (lane & 3)];
            }
            uint32_t bf[8][2];
#pragma unroll
            for (int nt = 0; nt < 8; nt++) {
                const int col = wn * 64 + nt * 8 + (lane >> 2);
                bf[nt][0] = bs[col * GSTRIDE + k0 + (lane & 3)];
                bf[nt][1] = bs[col * GSTRIDE + k0 + 4 + (lane & 3)];
            }
#pragma unroll
            for (int mt = 0; mt < 4; mt++)
#pragma unroll
                for (int nt = 0; nt < 8; nt++)
                    mma_tf32(c[mt][nt], af[mt], bf[nt]);
        }
    }

    // epilogue: scatter to g_qkv (tf32-rounded; Q plane scaled by CEXP)
#pragma unroll
    for (int mt = 0; mt < 4; mt++) {
#pragma unroll
        for (int half = 0; half < 2; half++) {
            const int m = m0 + wm * 64 + mt * 16 + (lane >> 2) + half * 8;
#pragma unroll
            for (int nt = 0; nt < 8; nt++) {
                const int n = n0 + wn * 64 + nt * 8 + 2 * (lane & 3);
                float v0 = c[mt][nt][2 * half + 0];
                float v1 = c[mt][nt][2 * half + 1];
                const int t = (n >= 2 * DD) ? 2 : ((n >= DD) ? 1 : 0);
                if (t == 0) { v0 *= CEXP; v1 *= CEXP; }
                const int r = n - t * DD;
                const int hh = r >> 6;
                const int e = r & 63;
                const int bb = m >> 11;
                const int ss = m & 2047;
                size_t idx = ((((size_t)t * BB + bb) * HH + hh) * SS + ss) * DKK + e;
                uint2 u;
                u.x = f2tf(v0);
                u.y = f2tf(v1);
                *(uint2*)&g_qkv[idx] = u;
            }
        }
    }
}

// ---------------------------------------------------------------------------
// tf32 tensor-core GEMM (O-proj): C = A(M,K) @ W(N,K)^T, plain output.
// BM=128, BN=128, BK=64; 8 warps (2m x 4n), warp tile 64x32.
// Smaller tiles -> 384 CTAs -> better wave balance (grid was 192 = 2 ragged waves).
// ---------------------------------------------------------------------------
#define OASLOT (128 * GSTRIDE)
#define OBSLOT (128 * GSTRIDE)
#define GEMMO_SMEM (GSTAGES * (OASLOT + OBSLOT) * 4)

__global__ __launch_bounds__(256, 1) void gemm_o(const float* __restrict__ A,
                                                 const float* __restrict__ W,
                                                 float* __restrict__ C,
                                                 int M, int N, int K) {
    extern __shared__ uint32_t gsm[];
    uint32_t* As = gsm;
    uint32_t* Bs = gsm + GSTAGES * OASLOT;

    const int tid  = threadIdx.x;
    const int lane = tid & 31;
    const int wid  = tid >> 5;
    const int wm   = wid >> 2;      // 0..1
    const int wn   = wid & 3;       // 0..3
    const int m0   = blockIdx.y * 128;
    const int n0   = blockIdx.x * 128;

    const int NT = K / 64;

    float c[4][4][4];
#pragma unroll
    for (int mt = 0; mt < 4; mt++)
#pragma unroll
        for (int nt = 0; nt < 4; nt++)
#pragma unroll
            for (int j = 0; j < 4; j++) c[mt][nt][j] = 0.0f;

    auto load_tile = [&](int kt, uint32_t* as, uint32_t* bs) {
        const float* Ab = A + (size_t)m0 * K + kt * 64;
        const float* Bb = W + (size_t)n0 * K + kt * 64;
#pragma unroll
        for (int i = 0; i < 8; i++) {
            const int ch = tid + i * 256;
            const int row = ch >> 4, c4 = (ch & 15) * 4;
            cp_async16(&as[row * GSTRIDE + c4], Ab + (size_t)row * K + c4);
        }
#pragma unroll
        for (int i = 0; i < 8; i++) {
            const int ch = tid + i * 256;
            const int row = ch >> 4, c4 = (ch & 15) * 4;
            cp_async16(&bs[row * GSTRIDE + c4], Bb + (size_t)row * K + c4);
        }
    };

    load_tile(0, As, Bs);
    cp_commit();

    for (int kt = 0; kt < NT; kt++) {
        cp_wait<0>();
        __syncthreads();

        if (kt + 1 < NT) {
            const int slot = (kt + 1) & 1;
            load_tile(kt + 1, As + slot * OASLOT, Bs + slot * OBSLOT);
        }
        cp_commit();

        const uint32_t* as = As + (kt & 1) * OASLOT;
        const uint32_t* bs = Bs + (kt & 1) * OBSLOT;

#pragma unroll
        for (int k0 = 0; k0 < 64; k0 += 8) {
            uint32_t af[4][4];
#pragma unroll
            for (int mt = 0; mt < 4; mt++) {
                const int row = wm * 64 + mt * 16 + (lane >> 2);
                af[mt][0] = as[row * GSTRIDE + k0 + (lane & 3)];
                af[mt][1] = as[(row + 8) * GSTRIDE + k0 + (lane & 3)];
                af[mt][2] = as[row * GSTRIDE + k0 + 4 + (lane & 3)];
                af[mt][3] = as[(row + 8) * GSTRIDE + k0 + 4 + (lane & 3)];
            }
            uint32_t bf[4][2];
#pragma unroll
            for (int nt = 0; nt < 4; nt++) {
                const int col = wn * 32 + nt * 8 + (lane >> 2);
                bf[nt][0] = bs[col * GSTRIDE + k0 + (lane & 3)];
                bf[nt][1] = bs[col * GSTRIDE + k0 + 4 + (lane & 3)];
            }
#pragma unroll
            for (int mt = 0; mt < 4; mt++)
#pragma unroll
                for (int nt = 0; nt < 4; nt++)
                    mma_tf32(c[mt][nt], af[mt], bf[nt]);
        }
    }

    // epilogue: plain row-major store
#pragma unroll
    for (int mt = 0; mt < 4; mt++) {
#pragma unroll
        for (int half = 0; half < 2; half++) {
            const int m = m0 + wm * 64 + mt * 16 + (lane >> 2) + half * 8;
#pragma unroll
            for (int nt = 0; nt < 4; nt++) {
                const int n = n0 + wn * 32 + nt * 8 + 2 * (lane & 3);
                float2 v = make_float2(c[mt][nt][2 * half], c[mt][nt][2 * half + 1]);
                *(float2*)&C[(size_t)m * N + n] = v;
            }
        }
    }
}

// ---------------------------------------------------------------------------
// Tensor-core causal flash attention (R14/R15-proven, unchanged).
// Br=128, Bc=64, dk=64; 128 threads = 4 warps; warp tile 32x64.
// Q pre-scaled (exp2 domain). Rescale-skip. smem 104448 B -> 2 CTAs/SM.
// ---------------------------------------------------------------------------
__global__ __launch_bounds__(128, 2) void attn_tc() {
    extern __shared__ uint32_t smx[];
    uint32_t* Qs = smx;                        // [128][68]
    uint32_t* Ks = smx + 128 * 68;             // [64][68]
    uint32_t* Vs = smx + 192 * 68;             // [64][68]
    uint32_t* Ps = smx + 256 * 68;             // [128][68]

    const int qt = (SS / 128 - 1) - blockIdx.x;   // largest work first
    const int h  = blockIdx.y;
    const int b  = blockIdx.z;
    const int tid  = threadIdx.x;
    const int lane = tid & 31;
    const int wm   = tid >> 5;   // 0..3

    const size_t plane = (size_t)BB * HH * SS * DKK;
    const size_t bh = (size_t)b * HH + h;
    const float* Qg = g_qkv + 0 * plane + bh * SS * DKK;
    const float* Kg = g_qkv + 1 * plane + bh * SS * DKK;
    const float* Vg = g_qkv + 2 * plane + bh * SS * DKK;

    const int lrow = tid >> 4;           // 0..7
    const int lc4  = (tid & 15) << 2;

#pragma unroll
    for (int i = 0; i < 16; i++) {
        const int row = lrow + i * 8;
        cp_async16(&Qs[row * 68 + lc4], Qg + ((size_t)(qt * 128 + row) << 6) + lc4);
    }
    cp_commit();
#pragma unroll
    for (int i = 0; i < 8; i++) {
        const int row = lrow + i * 8;
        cp_async16(&Ks[row * 68 + lc4], Kg + ((size_t)row << 6) + lc4);
    }
    cp_commit();
#pragma unroll
    for (int i = 0; i < 8; i++) {
        const int row = lrow + i * 8;
        cp_async16(&Vs[row * 68 + lc4], Vg + ((size_t)row << 6) + lc4);
    }
    cp_commit();

    float m_run[4], l_run[4], o[2][8][4];
#pragma unroll
    for (int r = 0; r < 4; r++) { m_run[r] = NEGINF; l_run[r] = 0.0f; }
#pragma unroll
    for (int mt = 0; mt < 2; mt++)
#pragma unroll
        for (int nt = 0; nt < 8; nt++)
#pragma unroll
            for (int j = 0; j < 4; j++) o[mt][nt][j] = 0.0f;

    const int ktmax = 2 * qt + 1;
    for (int kt = 0; kt <= ktmax; kt++) {
        cp_wait<1>();
        __syncthreads();

        float s[2][8][4];
#pragma unroll
        for (int mt = 0; mt < 2; mt++)
#pragma unroll
            for (int nt = 0; nt < 8; nt++)
#pragma unroll
                for (int j = 0; j < 4; j++) s[mt][nt][j] = 0.0f;

#pragma unroll
        for (int k0 = 0; k0 < 64; k0 += 8) {
            uint32_t af[2][4];
#pragma unroll
            for (int mt = 0; mt < 2; mt++) {
                const int row = wm * 32 + mt * 16 + (lane >> 2);
                af[mt][0] = Qs[row * 68 + k0 + (lane & 3)];
                af[mt][1] = Qs[(row + 8) * 68 + k0 + (lane & 3)];
                af[mt][2] = Qs[row * 68 + k0 + 4 + (lane & 3)];
                af[mt][3] = Qs[(row + 8) * 68 + k0 + 4 + (lane & 3)];
            }
            uint32_t bf[8][2];
#pragma unroll
            for (int nt = 0; nt < 8; nt++) {
                const int col = nt * 8 + (lane >> 2);
                bf[nt][0] = Ks[col * 68 + k0 + (lane & 3)];
                bf[nt][1] = Ks[col * 68 + k0 + 4 + (lane & 3)];
            }
#pragma unroll
            for (int mt = 0; mt < 2; mt++)
#pragma unroll
                for (int nt = 0; nt < 8; nt++)
                    mma_tf32(s[mt][nt], af[mt], bf[nt]);
        }

        if (kt >= 2 * qt) {
#pragma unroll
            for (int mt = 0; mt < 2; mt++)
#pragma unroll
                for (int cc = 0; cc < 4; cc++) {
                    const int row_g = qt * 128 + wm * 32 + mt * 16 + (lane >> 2) + 8 * (cc >> 1);
#pragma unroll
                    for (int nt = 0; nt < 8; nt++) {
                        const int col_g = kt * 64 + nt * 8 + 2 * (lane & 3) + (cc & 1);
                        if (col_g > row_g) s[mt][nt][cc] = NEGINF;
                    }
                }
        }

        // online softmax in exp2 domain (Q pre-scaled); rescale-skip
#pragma unroll
        for (int mt = 0; mt < 2; mt++)
#pragma unroll
            for (int half = 0; half < 2; half++) {
                const int rid = mt * 2 + half;
                float mv = NEGINF;
#pragma unroll
                for (int nt = 0; nt < 8; nt++)
                    mv = fmaxf(mv, fmaxf(s[mt][nt][2 * half], s[mt][nt][2 * half + 1]));
                mv = fmaxf(mv, __shfl_xor_sync(0xffffffffu, mv, 1));
                mv = fmaxf(mv, __shfl_xor_sync(0xffffffffu, mv, 2));
                const float mn = fmaxf(m_run[rid], mv);
                const bool same = (mn == m_run[rid]);
                float rs = 0.0f;
#pragma unroll
                for (int nt = 0; nt < 8; nt++)
#pragma unroll
                    for (int j = 0; j < 2; j++) {
                        float p = fexp2(s[mt][nt][2 * half + j] - mn);
                        s[mt][nt][2 * half + j] = p;
                        rs += p;
                    }
                rs += __shfl_xor_sync(0xffffffffu, rs, 1);
                rs += __shfl_xor_sync(0xffffffffu, rs, 2);
                if (same) {
                    l_run[rid] += rs;
                } else {
                    const float sc = fexp2(m_run[rid] - mn);
                    m_run[rid] = mn;
                    l_run[rid] = l_run[rid] * sc + rs;
#pragma unroll
                    for (int nt = 0; nt < 8; nt++)
#pragma unroll
                        for (int j = 0; j < 2; j++) o[mt][nt][2 * half + j] *= sc;
                }
            }

#pragma unroll
        for (int mt = 0; mt < 2; mt++)
#pragma unroll
            for (int half = 0; half < 2; half++) {
                const int row = wm * 32 + mt * 16 + (lane >> 2) + 8 * half;
#pragma unroll
                for (int nt = 0; nt < 8; nt++) {
                    const int col = nt * 8 + 2 * (lane & 3);
                    uint2 u;
                    u.x = f2tf(s[mt][nt][2 * half]);
                    u.y = f2tf(s[mt][nt][2 * half + 1]);
                    *(uint2*)&Ps[row * 68 + col] = u;
                }
            }
        __syncthreads();

        if (kt < ktmax) {
#pragma unroll
            for (int i = 0; i < 8; i++) {
                const int row = lrow + i * 8;
                cp_async16(&Ks[row * 68 + lc4],
                           Kg + ((size_t)((kt + 1) * 64 + row) << 6) + lc4);
            }
        }
        cp_commit();

        cp_wait<1>();
        __syncthreads();

#pragma unroll
        for (int k0 = 0; k0 < 64; k0 += 8) {
            uint32_t af[2][4];
#pragma unroll
            for (int mt = 0; mt < 2; mt++) {
                const int row = wm * 32 + mt * 16 + (lane >> 2);
                af[mt][0] = Ps[row * 68 + k0 + (lane & 3)];
                af[mt][1] = Ps[(row + 8) * 68 + k0 + (lane & 3)];
                af[mt][2] = Ps[row * 68 + k0 + 4 + (lane & 3)];
                af[mt][3] = Ps[(row + 8) * 68 + k0 + 4 + (lane & 3)];
            }
            uint32_t bf[8][2];
#pragma unroll
            for (int nt = 0; nt < 8; nt++) {
                const int col = nt * 8 + (lane >> 2);
                bf[nt][0] = Vs[(k0 + (lane & 3)) * 68 + col];
                bf[nt][1] = Vs[(k0 + 4 + (lane & 3)) * 68 + col];
            }
#pragma unroll
            for (int mt = 0; mt < 2; mt++)
#pragma unroll
                for (int nt = 0; nt < 8; nt++)
                    mma_tf32(o[mt][nt], af[mt], bf[nt]);
        }
        __syncthreads();

        if (kt < ktmax) {
#pragma unroll
            for (int i = 0; i < 8; i++) {
                const int row = lrow + i * 8;
                cp_async16(&Vs[row * 68 + lc4],
                           Vg + ((size_t)((kt + 1) * 64 + row) << 6) + lc4);
            }
        }
        cp_commit();
    }

    // epilogue: normalize, tf32-round, write g_obuf[b][s][d]
#pragma unroll
    for (int mt = 0; mt < 2; mt++)
#pragma unroll
        for (int half = 0; half < 2; half++) {
            const int rid = mt * 2 + half;
            const float inv = 1.0f / l_run[rid];
            const int row = qt * 128 + wm * 32 + mt * 16 + (lane >> 2) + 8 * half;
#pragma unroll
            for (int nt = 0; nt < 8; nt++) {
                const int d = h * 64 + nt * 8 + 2 * (lane & 3);
                uint2 u;
                u.x = f2tf(o[mt][nt][2 * half] * inv);
                u.y = f2tf(o[mt][nt][2 * half + 1] * inv);
                *(uint2*)&g_obuf[((size_t)b * SS + row) * DD + d] = u;
            }
        }
}

#define ATTN_SMEM (384 * 68 * 4)

// ---------------------------------------------------------------------------
extern "C" void kernel_launch(void* const* d_in, const int* in_sizes, int n_in,
                              void* d_out, int out_size) {
    const float* x   = (const float*)d_in[0];  // (4, 2048, 768)
    const float* wqk = (const float*)d_in[1];  // (3, 768, 768)
    const float* wo  = (const float*)d_in[2];  // (768, 768)
    float* out = (float*)d_out;                // (4, 2048, 768)
    (void)in_sizes; (void)n_in; (void)out_size;

    float *xr, *wqkvr, *wor, *obuf;
    cudaGetSymbolAddress((void**)&xr, g_xr);
    cudaGetSymbolAddress((void**)&wqkvr, g_wqkvr);
    cudaGetSymbolAddress((void**)&wor, g_wor);
    cudaGetSymbolAddress((void**)&obuf, g_obuf);

    cudaFuncSetAttribute(gemm_qkv, cudaFuncAttributeMaxDynamicSharedMemorySize, GEMM_SMEM);
    cudaFuncSetAttribute(gemm_o, cudaFuncAttributeMaxDynamicSharedMemorySize, GEMMO_SMEM);
    cudaFuncSetAttribute(attn_tc, cudaFuncAttributeMaxDynamicSharedMemorySize, ATTN_SMEM);

    // 0) pre-round inputs/weights to tf32
    {
        int n4x = MTOT * DD / 4, n4q = NQKV * DD / 4, n4o = DD * DD / 4;
        preround<<<(n4x + 255) / 256, 256>>>(xr, x, n4x);
        preround<<<(n4q + 255) / 256, 256>>>(wqkvr, wqk, n4q);
        preround<<<(n4o + 255) / 256, 256>>>(wor, wo, n4o);
    }

    // 1) QKV projection -> g_qkv (remapped, rounded, Q scaled by CEXP)
    gemm_qkv<<<dim3(NQKV / 128, MTOT / 256), 256, GEMM_SMEM>>>(xr, wqkvr, MTOT, NQKV, DD);

    // 2) Causal attention -> g_obuf (rounded)
    attn_tc<<<dim3(SS / 128, HH, BB), 128, ATTN_SMEM>>>();

    // 3) O projection -> out (128x128 tiles: 384 CTAs, better wave balance)
    gemm_o<<<dim3(DD / 128, MTOT / 128), 256, GEMMO_SMEM>>>(obuf, wor, out, MTOT, DD, DD);
}